// round 6
// baseline (speedup 1.0000x reference)
#include <cuda_runtime.h>
#include <cstdint>

#define D_IN   768
#define D_SAE  12288
#define T_LEN  64
#define KTOP   64
#define BATCH  32
#define NROWS  (BATCH * T_LEN)   // 2048

// ---------------- scratch (static device globals; no allocations) ----------------
__device__ __align__(16) float g_pre[(size_t)NROWS * D_SAE];     // 96 MB (exact fp32)
__device__ float g_gate[D_SAE];
__device__ int   g_topidx[NROWS * 128];
__device__ float g_topval[NROWS * 128];
__device__ int   g_zidx[NROWS * KTOP];
__device__ float g_zval[NROWS * KTOP];
__device__ float g_rowloss[NROWS];

// ---------------- helpers ----------------
__device__ __forceinline__ float2 unpack2(unsigned long long v) {
    float2 f;
    asm("mov.b64 {%0, %1}, %2;" : "=f"(f.x), "=f"(f.y) : "l"(v));
    return f;
}
__device__ __forceinline__ void fma2(unsigned long long& c, unsigned long long a, unsigned long long b) {
    asm("fma.rn.f32x2 %0, %1, %2, %0;" : "+l"(c) : "l"(a), "l"(b));
}
__device__ __forceinline__ unsigned int fkey(float v) {
    unsigned int u = __float_as_uint(v);
    return (u & 0x80000000u) ? ~u : (u | 0x80000000u);
}
__device__ __forceinline__ float keyToFloat(unsigned int k) {
    unsigned int u = (k & 0x80000000u) ? (k & 0x7FFFFFFFu) : ~k;
    return __uint_as_float(u);
}
// larger == (greater value) or (equal value, smaller index)  [jax top_k tie rule]
__device__ __forceinline__ unsigned long long makeComp(float v, int idx) {
    return ((unsigned long long)fkey(v) << 32) | (unsigned long long)(0xFFFFFFFFu - (unsigned int)idx);
}

// ======================================================================
// Kernel A: fp32 GEMM  pre[2048,12288] = X[2048,768] @ W[768,12288] + b
// 128x128 tile, BK=16, 256 threads, 8x8/thread, A duplicated in smem so
// both FFMA2 operands load as native 64-bit pairs (no packing MOVs).
// 48KB smem/CTA, 2 CTAs/SM.
// ======================================================================
__global__ __launch_bounds__(256, 2) void gemm_enc(const float* __restrict__ X,
                                                   const float* __restrict__ W,
                                                   const float* __restrict__ bias) {
    __shared__ __align__(16) float Ad[2][16][256];   // [k][2m]=[2m+1]=A[m]  (32KB)
    __shared__ __align__(16) float Bs[2][16][128];   // [k][n]               (16KB)

    const int tid  = threadIdx.x;
    const int row0 = blockIdx.y * 128;
    const int col0 = blockIdx.x * 128;
    const int tx = tid & 15, ty = tid >> 4;

    const int aRow = tid >> 2;           // 0..63
    const int aCol = (tid & 3) * 4;      // 0,4,8,12
    const int bRow = tid >> 5;           // 0..7
    const int bCol = (tid & 31) * 4;     // 0..124

    const float* Aptr = X + (size_t)row0 * D_IN;
    const float* Bptr = W + col0;

    float4 a0, a1, b0, b1;
    a0 = *(const float4*)(Aptr + (size_t)aRow * D_IN + aCol);
    a1 = *(const float4*)(Aptr + (size_t)(aRow + 64) * D_IN + aCol);
    b0 = *(const float4*)(Bptr + (size_t)bRow * D_SAE + bCol);
    b1 = *(const float4*)(Bptr + (size_t)(bRow + 8) * D_SAE + bCol);
    {
        const float av0[4] = {a0.x, a0.y, a0.z, a0.w};
        const float av1[4] = {a1.x, a1.y, a1.z, a1.w};
#pragma unroll
        for (int c = 0; c < 4; ++c) {
            float2 d0 = {av0[c], av0[c]};
            float2 d1 = {av1[c], av1[c]};
            *(float2*)&Ad[0][aCol + c][2 * aRow] = d0;
            *(float2*)&Ad[0][aCol + c][2 * (aRow + 64)] = d1;
        }
        *(float4*)&Bs[0][bRow][bCol]     = b0;
        *(float4*)&Bs[0][bRow + 8][bCol] = b1;
    }
    __syncthreads();

    unsigned long long cc[8][4];
#pragma unroll
    for (int i = 0; i < 8; ++i)
#pragma unroll
        for (int j = 0; j < 4; ++j) cc[i][j] = 0ull;

    const int NKT = D_IN / 16;  // 48
    for (int kt = 0; kt < NKT; ++kt) {
        const int cur = kt & 1;
        if (kt < NKT - 1) {
            const int k0 = (kt + 1) * 16;
            a0 = *(const float4*)(Aptr + (size_t)aRow * D_IN + k0 + aCol);
            a1 = *(const float4*)(Aptr + (size_t)(aRow + 64) * D_IN + k0 + aCol);
            b0 = *(const float4*)(Bptr + (size_t)(k0 + bRow) * D_SAE + bCol);
            b1 = *(const float4*)(Bptr + (size_t)(k0 + bRow + 8) * D_SAE + bCol);
        }
#pragma unroll
        for (int k = 0; k < 16; ++k) {
            ulonglong2 ad01 = *(const ulonglong2*)&Ad[cur][k][ty * 16];
            ulonglong2 ad23 = *(const ulonglong2*)&Ad[cur][k][ty * 16 + 4];
            ulonglong2 ad45 = *(const ulonglong2*)&Ad[cur][k][ty * 16 + 8];
            ulonglong2 ad67 = *(const ulonglong2*)&Ad[cur][k][ty * 16 + 12];
            ulonglong2 bp01 = *(const ulonglong2*)&Bs[cur][k][tx * 8];
            ulonglong2 bp23 = *(const ulonglong2*)&Bs[cur][k][tx * 8 + 4];
            unsigned long long ad[8] = {ad01.x, ad01.y, ad23.x, ad23.y,
                                        ad45.x, ad45.y, ad67.x, ad67.y};
            unsigned long long bp[4] = {bp01.x, bp01.y, bp23.x, bp23.y};
#pragma unroll
            for (int i = 0; i < 8; ++i)
#pragma unroll
                for (int j = 0; j < 4; ++j) fma2(cc[i][j], ad[i], bp[j]);
        }
        if (kt < NKT - 1) {
            const int nxt = cur ^ 1;
            const float av0[4] = {a0.x, a0.y, a0.z, a0.w};
            const float av1[4] = {a1.x, a1.y, a1.z, a1.w};
#pragma unroll
            for (int c = 0; c < 4; ++c) {
                float2 d0 = {av0[c], av0[c]};
                float2 d1 = {av1[c], av1[c]};
                *(float2*)&Ad[nxt][aCol + c][2 * aRow] = d0;
                *(float2*)&Ad[nxt][aCol + c][2 * (aRow + 64)] = d1;
            }
            *(float4*)&Bs[nxt][bRow][bCol]     = b0;
            *(float4*)&Bs[nxt][bRow + 8][bCol] = b1;
        }
        __syncthreads();
    }

    // epilogue: bias add, 2x STG.128 per row
    const float4 bb0 = *(const float4*)(bias + col0 + tx * 8);
    const float4 bb1 = *(const float4*)(bias + col0 + tx * 8 + 4);
#pragma unroll
    for (int i = 0; i < 8; ++i) {
        const float2 v0 = unpack2(cc[i][0]);
        const float2 v1 = unpack2(cc[i][1]);
        const float2 v2 = unpack2(cc[i][2]);
        const float2 v3 = unpack2(cc[i][3]);
        float4 o0 = {v0.x + bb0.x, v0.y + bb0.y, v1.x + bb0.z, v1.y + bb0.w};
        float4 o1 = {v2.x + bb1.x, v2.y + bb1.y, v3.x + bb1.z, v3.y + bb1.w};
        size_t base = (size_t)(row0 + ty * 8 + i) * D_SAE + col0 + tx * 8;
        *(float4*)&g_pre[base]     = o0;
        *(float4*)&g_pre[base + 4] = o1;
    }
}

// ======================================================================
// Kernel B: exact top-128 per row; single DRAM pass (row held in regs).
// ======================================================================
#define TK_CAP 3072
__global__ __launch_bounds__(256) void topk128() {
    __shared__ unsigned int hist[4096];
    __shared__ unsigned long long cand[TK_CAP];
    __shared__ unsigned int chunkSum[16];
    __shared__ int s_bin;
    __shared__ unsigned int s_cntHi, s_cntCand;

    const int row = blockIdx.x, tid = threadIdx.x;
    const float* rp = g_pre + (size_t)row * D_SAE;

    for (int i = tid; i < 4096; i += 256) hist[i] = 0;
    if (tid == 0) { s_cntHi = 0; s_cntCand = 0; }
    __syncthreads();

    float v[48];
#pragma unroll
    for (int i = 0; i < 12; ++i) {
        const float4 q = *(const float4*)(rp + (size_t)(tid + i * 256) * 4);
        v[i * 4 + 0] = q.x; v[i * 4 + 1] = q.y; v[i * 4 + 2] = q.z; v[i * 4 + 3] = q.w;
    }
#pragma unroll
    for (int i = 0; i < 48; ++i) atomicAdd(&hist[fkey(v[i]) >> 20], 1u);
    __syncthreads();

    if (tid < 16) {
        unsigned int s = 0;
        for (int j = 0; j < 256; ++j) s += hist[tid * 256 + j];
        chunkSum[tid] = s;
    }
    __syncthreads();
    if (tid == 0) {
        unsigned int cum = 0; int cb;
        for (cb = 15; cb > 0; --cb) {
            if (cum + chunkSum[cb] >= 128u) break;
            cum += chunkSum[cb];
        }
        int bin;
        for (bin = cb * 256 + 255; bin > cb * 256; --bin) {
            if (cum + hist[bin] >= 128u) break;
            cum += hist[bin];
        }
        s_bin = bin;
    }
    __syncthreads();

    const int tb = s_bin;
#pragma unroll
    for (int i = 0; i < 48; ++i) {
        const unsigned int k = fkey(v[i]);
        const int bin = (int)(k >> 20);
        if (bin >= tb) {
            const int idx = (tid + (i >> 2) * 256) * 4 + (i & 3);
            if (bin > tb) {
                unsigned int p = atomicAdd(&s_cntHi, 1u);
                g_topidx[row * 128 + p] = idx;
                g_topval[row * 128 + p] = v[i];
            } else {
                unsigned int q = atomicAdd(&s_cntCand, 1u);
                if (q < TK_CAP) cand[q] = makeComp(v[i], idx);
            }
        }
    }
    __syncthreads();

    const int need = 128 - (int)s_cntHi;
    const int nc = min((int)s_cntCand, TK_CAP);
    for (int c = tid; c < nc; c += 256) {
        const unsigned long long me = cand[c];
        int r = 0;
        for (int j = 0; j < nc; ++j) r += (cand[j] > me);
        if (r < need) {
            const int pos = (int)s_cntHi + r;
            g_topidx[row * 128 + pos] = (int)(0xFFFFFFFFu - (unsigned int)me);
            g_topval[row * 128 + pos] = keyToFloat((unsigned int)(me >> 32));
        }
    }
}

// ======================================================================
// gate precompute
// ======================================================================
__global__ __launch_bounds__(256) void gate_kernel(const float* __restrict__ gate_raw) {
    const int i = blockIdx.x * 256 + threadIdx.x;
    if (i < D_SAE) g_gate[i] = 1.0f / (1.0f + expf(-gate_raw[i]));
}

// ======================================================================
// Kernel C: sequential scan; exact top-64 from <=192 candidates per step.
// ======================================================================
__global__ __launch_bounds__(256) void scan_kernel() {
    __shared__ unsigned int bitmap[D_SAE / 32];
    __shared__ int prevIdx[KTOP];
    __shared__ float prevVal[KTOP];
    __shared__ unsigned long long cand[208];
    __shared__ int tmpIdx[KTOP];
    __shared__ float tmpVal[KTOP];
    __shared__ int s_ncand;

    const int b = blockIdx.x, tid = threadIdx.x;
    for (int i = tid; i < D_SAE / 32; i += 256) bitmap[i] = 0;
    int nprev = 0;
    __syncthreads();

    for (int t = 0; t < T_LEN; ++t) {
        const int row = b * T_LEN + t;
        if (tid == 0) s_ncand = nprev;
        __syncthreads();

        if (tid < nprev) {
            const int idx = prevIdx[tid];
            const float pre = g_pre[(size_t)row * D_SAE + idx];
            cand[tid] = makeComp(g_gate[idx] * prevVal[tid] + pre, idx);
        }
        if (tid < 128) {
            const int idx = g_topidx[row * 128 + tid];
            if (!((bitmap[idx >> 5] >> (idx & 31)) & 1u)) {
                const int p = atomicAdd(&s_ncand, 1);
                cand[p] = makeComp(g_topval[row * 128 + tid], idx);
            }
        }
        __syncthreads();

        const int n = s_ncand;
        if (tid < n) {
            const unsigned long long me = cand[tid];
            int r = 0;
            for (int j = 0; j < n; ++j) r += (cand[j] > me);
            if (r < KTOP) {
                tmpIdx[r] = (int)(0xFFFFFFFFu - (unsigned int)me);
                tmpVal[r] = fmaxf(keyToFloat((unsigned int)(me >> 32)), 0.0f);
            }
        }
        __syncthreads();

        if (tid < nprev) atomicAnd(&bitmap[prevIdx[tid] >> 5], ~(1u << (prevIdx[tid] & 31)));
        __syncthreads();

        if (tid < KTOP) {
            const int idx = tmpIdx[tid];
            const float v = tmpVal[tid];
            prevIdx[tid] = idx; prevVal[tid] = v;
            atomicOr(&bitmap[idx >> 5], 1u << (idx & 31));
            g_zidx[row * KTOP + tid] = idx;
            g_zval[row * KTOP + tid] = v;
        }
        nprev = KTOP;
        __syncthreads();
    }
}

// ======================================================================
// Kernel D: sparse decode + per-row squared error. (xhat only 4B-aligned)
// ======================================================================
__global__ __launch_bounds__(192) void decode_kernel(const float* __restrict__ X,
                                                     const float* __restrict__ Wd,
                                                     const float* __restrict__ b_dec,
                                                     float* __restrict__ xhat) {
    __shared__ int sIdx[KTOP];
    __shared__ float sVal[KTOP];
    __shared__ float red[192];
    const int row = blockIdx.x, tid = threadIdx.x;
    if (tid < KTOP) {
        sIdx[tid] = g_zidx[row * KTOP + tid];
        sVal[tid] = g_zval[row * KTOP + tid];
    }
    __syncthreads();

    float4 acc = *(const float4*)(b_dec + tid * 4);
#pragma unroll 4
    for (int k = 0; k < KTOP; ++k) {
        const float v = sVal[k];
        const float4 w = *(const float4*)(Wd + (size_t)sIdx[k] * D_IN + tid * 4);
        acc.x += v * w.x; acc.y += v * w.y; acc.z += v * w.z; acc.w += v * w.w;
    }
    float* op = xhat + (size_t)row * D_IN + tid * 4;
    op[0] = acc.x; op[1] = acc.y; op[2] = acc.z; op[3] = acc.w;

    const float4 xv = *(const float4*)(X + (size_t)row * D_IN + tid * 4);
    const float dx = acc.x - xv.x, dy = acc.y - xv.y, dz = acc.z - xv.z, dw = acc.w - xv.w;
    red[tid] = dx * dx + dy * dy + dz * dz + dw * dw;
    __syncthreads();
    for (int s = 96; s >= 6; s >>= 1) {
        if (tid < s) red[tid] += red[tid + s];
        __syncthreads();
    }
    if (tid == 0) {
        float total = 0.f;
        for (int i = 0; i < 6; ++i) total += red[i];
        g_rowloss[row] = total;
    }
}

// ======================================================================
// Finalization
// ======================================================================
__global__ void zero_zlast(float* __restrict__ z) {
    const int i = blockIdx.x * blockDim.x + threadIdx.x;
    if (i < BATCH * D_SAE) z[i] = 0.0f;
}
__global__ void scatter_zlast(float* __restrict__ z) {
    const int gid = blockIdx.x * blockDim.x + threadIdx.x;
    if (gid < BATCH * KTOP) {
        const int b = gid >> 6, k = gid & 63;
        const int row = b * T_LEN + (T_LEN - 1);
        z[(size_t)b * D_SAE + g_zidx[row * KTOP + k]] = g_zval[row * KTOP + k];
    }
}
__global__ __launch_bounds__(1024) void loss_kernel(float* __restrict__ out) {
    __shared__ float red[1024];
    const int tid = threadIdx.x;
    red[tid] = g_rowloss[tid] + g_rowloss[tid + 1024];
    __syncthreads();
    for (int s = 512; s > 0; s >>= 1) {
        if (tid < s) red[tid] += red[tid + s];
        __syncthreads();
    }
    if (tid == 0) out[0] = red[0] / (float)NROWS;
}

// ======================================================================
extern "C" void kernel_launch(void* const* d_in, const int* in_sizes, int n_in,
                              void* d_out, int out_size) {
    const float* x        = (const float*)d_in[0];
    const float* W_enc    = (const float*)d_in[1];
    const float* W_dec    = (const float*)d_in[2];
    const float* b_enc    = (const float*)d_in[3];
    const float* b_dec    = (const float*)d_in[4];
    const float* gate_raw = (const float*)d_in[5];

    float* out       = (float*)d_out;
    float* out_loss  = out;
    float* out_xhat  = out + 1;
    float* out_zlast = out + 1 + (size_t)NROWS * D_IN;

    gate_kernel<<<(D_SAE + 255) / 256, 256>>>(gate_raw);
    dim3 gGrid(D_SAE / 128, NROWS / 128);  // (96, 16)
    gemm_enc<<<gGrid, 256>>>(x, W_enc, b_enc);
    topk128<<<NROWS, 256>>>();
    scan_kernel<<<BATCH, 256>>>();
    decode_kernel<<<NROWS, 192>>>(x, W_dec, b_dec, out_xhat);
    zero_zlast<<<(BATCH * D_SAE + 255) / 256, 256>>>(out_zlast);
    scatter_zlast<<<(BATCH * KTOP + 255) / 256, 256>>>(out_zlast);
    loss_kernel<<<1, 1024>>>(out_loss);
}

// round 7
// speedup vs baseline: 1.3066x; 1.3066x over previous
#include <cuda_runtime.h>
#include <cstdint>

#define D_IN   768
#define D_SAE  12288
#define T_LEN  64
#define KTOP   64
#define BATCH  32
#define NROWS  (BATCH * T_LEN)   // 2048

// ---------------- scratch (static device globals; no allocations) ----------------
__device__ __align__(16) float g_pre[(size_t)NROWS * D_SAE];     // 96 MB (exact fp32)
__device__ float g_gate[D_SAE];
__device__ int   g_topidx[NROWS * 128];
__device__ float g_topval[NROWS * 128];
__device__ int   g_zidx[NROWS * KTOP];
__device__ float g_zval[NROWS * KTOP];
__device__ float g_rowloss[NROWS];

// ---------------- helpers ----------------
__device__ __forceinline__ unsigned long long pack2(float x, float y) {
    unsigned long long r;
    asm("mov.b64 %0, {%1, %2};" : "=l"(r) : "f"(x), "f"(y));
    return r;
}
__device__ __forceinline__ float2 unpack2(unsigned long long v) {
    float2 f;
    asm("mov.b64 {%0, %1}, %2;" : "=f"(f.x), "=f"(f.y) : "l"(v));
    return f;
}
__device__ __forceinline__ void fma2(unsigned long long& c, unsigned long long a, unsigned long long b) {
    asm("fma.rn.f32x2 %0, %1, %2, %0;" : "+l"(c) : "l"(a), "l"(b));
}
__device__ __forceinline__ unsigned int fkey(float v) {
    unsigned int u = __float_as_uint(v);
    return (u & 0x80000000u) ? ~u : (u | 0x80000000u);
}
__device__ __forceinline__ float keyToFloat(unsigned int k) {
    unsigned int u = (k & 0x80000000u) ? (k & 0x7FFFFFFFu) : ~k;
    return __uint_as_float(u);
}
// larger == (greater value) or (equal value, smaller index)  [jax top_k tie rule]
__device__ __forceinline__ unsigned long long makeComp(float v, int idx) {
    return ((unsigned long long)fkey(v) << 32) | (unsigned long long)(0xFFFFFFFFu - (unsigned int)idx);
}

// ======================================================================
// Kernel A: fp32 GEMM (R2 proven variant).
// 128x128 tile, BK=16, 256 threads, 8x8/thread, f32x2 packed FMA.
// ======================================================================
__global__ __launch_bounds__(256, 1) void gemm_enc(const float* __restrict__ X,
                                                   const float* __restrict__ W,
                                                   const float* __restrict__ bias) {
    __shared__ __align__(16) float As[2][16][128];
    __shared__ __align__(16) float Bs[2][16][128];

    const int tid  = threadIdx.x;
    const int row0 = blockIdx.y * 128;
    const int col0 = blockIdx.x * 128;
    const int tx = tid & 15, ty = tid >> 4;

    const int aRow = tid >> 2;           // 0..63
    const int aCol = (tid & 3) * 4;      // 0,4,8,12
    const int bRow = tid >> 5;           // 0..7
    const int bCol = (tid & 31) * 4;     // 0..124

    const float* Aptr = X + (size_t)row0 * D_IN;
    const float* Bptr = W + col0;

    float4 a0, a1, b0, b1;
    a0 = *(const float4*)(Aptr + (size_t)aRow * D_IN + aCol);
    a1 = *(const float4*)(Aptr + (size_t)(aRow + 64) * D_IN + aCol);
    b0 = *(const float4*)(Bptr + (size_t)bRow * D_SAE + bCol);
    b1 = *(const float4*)(Bptr + (size_t)(bRow + 8) * D_SAE + bCol);
    As[0][aCol + 0][aRow] = a0.x; As[0][aCol + 1][aRow] = a0.y;
    As[0][aCol + 2][aRow] = a0.z; As[0][aCol + 3][aRow] = a0.w;
    As[0][aCol + 0][aRow + 64] = a1.x; As[0][aCol + 1][aRow + 64] = a1.y;
    As[0][aCol + 2][aRow + 64] = a1.z; As[0][aCol + 3][aRow + 64] = a1.w;
    *(float4*)&Bs[0][bRow][bCol]     = b0;
    *(float4*)&Bs[0][bRow + 8][bCol] = b1;
    __syncthreads();

    unsigned long long cc[4][8];
#pragma unroll
    for (int i = 0; i < 4; ++i)
#pragma unroll
        for (int j = 0; j < 8; ++j) cc[i][j] = 0ull;

    const int NKT = D_IN / 16;  // 48
    for (int kt = 0; kt < NKT; ++kt) {
        const int cur = kt & 1;
        if (kt < NKT - 1) {
            const int k0 = (kt + 1) * 16;
            a0 = *(const float4*)(Aptr + (size_t)aRow * D_IN + k0 + aCol);
            a1 = *(const float4*)(Aptr + (size_t)(aRow + 64) * D_IN + k0 + aCol);
            b0 = *(const float4*)(Bptr + (size_t)(k0 + bRow) * D_SAE + bCol);
            b1 = *(const float4*)(Bptr + (size_t)(k0 + bRow + 8) * D_SAE + bCol);
        }
#pragma unroll
        for (int k = 0; k < 16; ++k) {
            ulonglong2 aa01 = *(const ulonglong2*)&As[cur][k][ty * 4];
            ulonglong2 aa23 = *(const ulonglong2*)&As[cur][k][64 + ty * 4];
            float4 bv0 = *(const float4*)&Bs[cur][k][tx * 4];
            float4 bv1 = *(const float4*)&Bs[cur][k][64 + tx * 4];
            unsigned long long av[4] = {aa01.x, aa01.y, aa23.x, aa23.y};
            unsigned long long bb[8] = {pack2(bv0.x, bv0.x), pack2(bv0.y, bv0.y),
                                        pack2(bv0.z, bv0.z), pack2(bv0.w, bv0.w),
                                        pack2(bv1.x, bv1.x), pack2(bv1.y, bv1.y),
                                        pack2(bv1.z, bv1.z), pack2(bv1.w, bv1.w)};
#pragma unroll
            for (int i = 0; i < 4; ++i)
#pragma unroll
                for (int j = 0; j < 8; ++j) fma2(cc[i][j], av[i], bb[j]);
        }
        if (kt < NKT - 1) {
            const int nxt = cur ^ 1;
            As[nxt][aCol + 0][aRow] = a0.x; As[nxt][aCol + 1][aRow] = a0.y;
            As[nxt][aCol + 2][aRow] = a0.z; As[nxt][aCol + 3][aRow] = a0.w;
            As[nxt][aCol + 0][aRow + 64] = a1.x; As[nxt][aCol + 1][aRow + 64] = a1.y;
            As[nxt][aCol + 2][aRow + 64] = a1.z; As[nxt][aCol + 3][aRow + 64] = a1.w;
            *(float4*)&Bs[nxt][bRow][bCol]     = b0;
            *(float4*)&Bs[nxt][bRow + 8][bCol] = b1;
        }
        __syncthreads();
    }

    float bc[8];
#pragma unroll
    for (int j = 0; j < 8; ++j) bc[j] = bias[col0 + (j >> 2) * 64 + tx * 4 + (j & 3)];

#pragma unroll
    for (int i = 0; i < 4; ++i) {
        const int m = (i >> 1) * 64 + ty * 4 + (i & 1) * 2;
        float2 v[8];
#pragma unroll
        for (int j = 0; j < 8; ++j) v[j] = unpack2(cc[i][j]);
        size_t base = (size_t)(row0 + m) * D_SAE + col0;
        float4 o;
        o.x = v[0].x + bc[0]; o.y = v[1].x + bc[1]; o.z = v[2].x + bc[2]; o.w = v[3].x + bc[3];
        *(float4*)&g_pre[base + tx * 4] = o;
        o.x = v[4].x + bc[4]; o.y = v[5].x + bc[5]; o.z = v[6].x + bc[6]; o.w = v[7].x + bc[7];
        *(float4*)&g_pre[base + 64 + tx * 4] = o;
        base += D_SAE;
        o.x = v[0].y + bc[0]; o.y = v[1].y + bc[1]; o.z = v[2].y + bc[2]; o.w = v[3].y + bc[3];
        *(float4*)&g_pre[base + tx * 4] = o;
        o.x = v[4].y + bc[4]; o.y = v[5].y + bc[5]; o.z = v[6].y + bc[6]; o.w = v[7].y + bc[7];
        *(float4*)&g_pre[base + 64 + tx * 4] = o;
    }
}

// ======================================================================
// Kernel B: exact top-128 per row; single DRAM pass (row held in regs).
// ======================================================================
#define TK_CAP 3072
__global__ __launch_bounds__(256) void topk128() {
    __shared__ unsigned int hist[4096];
    __shared__ __align__(16) unsigned long long cand[TK_CAP];
    __shared__ unsigned int chunkSum[16];
    __shared__ int s_bin;
    __shared__ unsigned int s_cntHi, s_cntCand;

    const int row = blockIdx.x, tid = threadIdx.x;
    const float* rp = g_pre + (size_t)row * D_SAE;

    for (int i = tid; i < 4096; i += 256) hist[i] = 0;
    if (tid == 0) { s_cntHi = 0; s_cntCand = 0; }
    __syncthreads();

    float v[48];
#pragma unroll
    for (int i = 0; i < 12; ++i) {
        const float4 q = *(const float4*)(rp + (size_t)(tid + i * 256) * 4);
        v[i * 4 + 0] = q.x; v[i * 4 + 1] = q.y; v[i * 4 + 2] = q.z; v[i * 4 + 3] = q.w;
    }
#pragma unroll
    for (int i = 0; i < 48; ++i) atomicAdd(&hist[fkey(v[i]) >> 20], 1u);
    __syncthreads();

    if (tid < 16) {
        unsigned int s = 0;
        for (int j = 0; j < 256; ++j) s += hist[tid * 256 + j];
        chunkSum[tid] = s;
    }
    __syncthreads();
    if (tid == 0) {
        unsigned int cum = 0; int cb;
        for (cb = 15; cb > 0; --cb) {
            if (cum + chunkSum[cb] >= 128u) break;
            cum += chunkSum[cb];
        }
        int bin;
        for (bin = cb * 256 + 255; bin > cb * 256; --bin) {
            if (cum + hist[bin] >= 128u) break;
            cum += hist[bin];
        }
        s_bin = bin;
    }
    __syncthreads();

    const int tb = s_bin;
#pragma unroll
    for (int i = 0; i < 48; ++i) {
        const unsigned int k = fkey(v[i]);
        const int bin = (int)(k >> 20);
        if (bin >= tb) {
            const int idx = (tid + (i >> 2) * 256) * 4 + (i & 3);
            if (bin > tb) {
                unsigned int p = atomicAdd(&s_cntHi, 1u);
                g_topidx[row * 128 + p] = idx;
                g_topval[row * 128 + p] = v[i];
            } else {
                unsigned int q = atomicAdd(&s_cntCand, 1u);
                if (q < TK_CAP) cand[q] = makeComp(v[i], idx);
            }
        }
    }
    __syncthreads();

    const int need = 128 - (int)s_cntHi;
    const int nc = min((int)s_cntCand, TK_CAP);
    for (int c = tid; c < nc; c += 256) {
        const unsigned long long me = cand[c];
        int r = 0;
        for (int j = 0; j < nc; ++j) r += (cand[j] > me);
        if (r < need) {
            const int pos = (int)s_cntHi + r;
            g_topidx[row * 128 + pos] = (int)(0xFFFFFFFFu - (unsigned int)me);
            g_topval[row * 128 + pos] = keyToFloat((unsigned int)(me >> 32));
        }
    }
}

// ======================================================================
// gate precompute + output-zero kernels (also used to pad launch order)
// ======================================================================
__global__ __launch_bounds__(256) void gate_kernel(const float* __restrict__ gate_raw) {
    const int i = blockIdx.x * 256 + threadIdx.x;
    if (i < D_SAE) g_gate[i] = 1.0f / (1.0f + expf(-gate_raw[i]));
}
__global__ void zero_half(float* __restrict__ z) {
    const int i = blockIdx.x * blockDim.x + threadIdx.x;
    if (i < BATCH * D_SAE / 2) z[i] = 0.0f;
}

// ======================================================================
// Kernel C: sequential scan. Sentinel-padded, unrolled rank loop.
// ======================================================================
__global__ __launch_bounds__(256) void scan_kernel() {
    __shared__ unsigned int bitmap[D_SAE / 32];
    __shared__ int prevIdx[KTOP];
    __shared__ float prevVal[KTOP];
    __shared__ __align__(16) unsigned long long cand[224];
    __shared__ int tmpIdx[KTOP];
    __shared__ float tmpVal[KTOP];
    __shared__ int s_ncand;

    const int b = blockIdx.x, tid = threadIdx.x;
    for (int i = tid; i < D_SAE / 32; i += 256) bitmap[i] = 0;
    int nprev = 0;
    __syncthreads();

    for (int t = 0; t < T_LEN; ++t) {
        const int row = b * T_LEN + t;
        if (tid == 0) s_ncand = nprev;
        if (tid < 224) cand[tid] = 0ull;   // sentinels (rank below everything)
        __syncthreads();

        if (tid < nprev) {
            const int idx = prevIdx[tid];
            const float pre = g_pre[(size_t)row * D_SAE + idx];
            cand[tid] = makeComp(g_gate[idx] * prevVal[tid] + pre, idx);
        }
        if (tid < 128) {
            const int idx = g_topidx[row * 128 + tid];
            if (!((bitmap[idx >> 5] >> (idx & 31)) & 1u)) {
                const int p = atomicAdd(&s_ncand, 1);
                cand[p] = makeComp(g_topval[row * 128 + tid], idx);
            }
        }
        __syncthreads();

        const int n = s_ncand;
        const int nP = (n + 7) & ~7;
        if (tid < n) {
            const unsigned long long me = cand[tid];
            int r = 0;
            for (int j = 0; j < nP; j += 8) {
                const ulonglong2 c0 = *(const ulonglong2*)&cand[j];
                const ulonglong2 c1 = *(const ulonglong2*)&cand[j + 2];
                const ulonglong2 c2 = *(const ulonglong2*)&cand[j + 4];
                const ulonglong2 c3 = *(const ulonglong2*)&cand[j + 6];
                r += (c0.x > me) + (c0.y > me) + (c1.x > me) + (c1.y > me)
                   + (c2.x > me) + (c2.y > me) + (c3.x > me) + (c3.y > me);
            }
            if (r < KTOP) {
                tmpIdx[r] = (int)(0xFFFFFFFFu - (unsigned int)cand[tid]);
                tmpVal[r] = fmaxf(keyToFloat((unsigned int)(cand[tid] >> 32)), 0.0f);
            }
        }
        __syncthreads();

        if (tid < nprev) atomicAnd(&bitmap[prevIdx[tid] >> 5], ~(1u << (prevIdx[tid] & 31)));
        __syncthreads();

        if (tid < KTOP) {
            const int idx = tmpIdx[tid];
            const float v = tmpVal[tid];
            prevIdx[tid] = idx; prevVal[tid] = v;
            atomicOr(&bitmap[idx >> 5], 1u << (idx & 31));
            g_zidx[row * KTOP + tid] = idx;
            g_zval[row * KTOP + tid] = v;
        }
        nprev = KTOP;
        __syncthreads();
    }
}

// ======================================================================
// Kernel D: sparse decode + per-row squared error. (xhat only 4B-aligned)
// ======================================================================
__global__ __launch_bounds__(192) void decode_kernel(const float* __restrict__ X,
                                                     const float* __restrict__ Wd,
                                                     const float* __restrict__ b_dec,
                                                     float* __restrict__ xhat) {
    __shared__ int sIdx[KTOP];
    __shared__ float sVal[KTOP];
    __shared__ float red[192];
    const int row = blockIdx.x, tid = threadIdx.x;
    if (tid < KTOP) {
        sIdx[tid] = g_zidx[row * KTOP + tid];
        sVal[tid] = g_zval[row * KTOP + tid];
    }
    __syncthreads();

    float4 acc = *(const float4*)(b_dec + tid * 4);
#pragma unroll 4
    for (int k = 0; k < KTOP; ++k) {
        const float v = sVal[k];
        const float4 w = *(const float4*)(Wd + (size_t)sIdx[k] * D_IN + tid * 4);
        acc.x += v * w.x; acc.y += v * w.y; acc.z += v * w.z; acc.w += v * w.w;
    }
    float* op = xhat + (size_t)row * D_IN + tid * 4;
    op[0] = acc.x; op[1] = acc.y; op[2] = acc.z; op[3] = acc.w;

    const float4 xv = *(const float4*)(X + (size_t)row * D_IN + tid * 4);
    const float dx = acc.x - xv.x, dy = acc.y - xv.y, dz = acc.z - xv.z, dw = acc.w - xv.w;
    red[tid] = dx * dx + dy * dy + dz * dz + dw * dw;
    __syncthreads();
    for (int s = 96; s >= 6; s >>= 1) {
        if (tid < s) red[tid] += red[tid + s];
        __syncthreads();
    }
    if (tid == 0) {
        float total = 0.f;
        for (int i = 0; i < 6; ++i) total += red[i];
        g_rowloss[row] = total;
    }
}

// ======================================================================
// Finalization
// ======================================================================
__global__ void scatter_zlast(float* __restrict__ z) {
    const int gid = blockIdx.x * blockDim.x + threadIdx.x;
    if (gid < BATCH * KTOP) {
        const int b = gid >> 6, k = gid & 63;
        const int row = b * T_LEN + (T_LEN - 1);
        z[(size_t)b * D_SAE + g_zidx[row * KTOP + k]] = g_zval[row * KTOP + k];
    }
}
__global__ __launch_bounds__(1024) void loss_kernel(float* __restrict__ out) {
    __shared__ float red[1024];
    const int tid = threadIdx.x;
    red[tid] = g_rowloss[tid] + g_rowloss[tid + 1024];
    __syncthreads();
    for (int s = 512; s > 0; s >>= 1) {
        if (tid < s) red[tid] += red[tid + s];
        __syncthreads();
    }
    if (tid == 0) out[0] = red[0] / (float)NROWS;
}

// ======================================================================
extern "C" void kernel_launch(void* const* d_in, const int* in_sizes, int n_in,
                              void* d_out, int out_size) {
    const float* x        = (const float*)d_in[0];
    const float* W_enc    = (const float*)d_in[1];
    const float* W_dec    = (const float*)d_in[2];
    const float* b_enc    = (const float*)d_in[3];
    const float* b_dec    = (const float*)d_in[4];
    const float* gate_raw = (const float*)d_in[5];

    float* out       = (float*)d_out;
    float* out_loss  = out;
    float* out_xhat  = out + 1;
    float* out_zlast = out + 1 + (size_t)NROWS * D_IN;

    const int halfN = BATCH * D_SAE / 2;
    // launches 1-3 are cheap & independent; gemm is launch #4 (ncu profiles #4)
    zero_half<<<(halfN + 255) / 256, 256>>>(out_zlast);
    zero_half<<<(halfN + 255) / 256, 256>>>(out_zlast + halfN);
    gate_kernel<<<(D_SAE + 255) / 256, 256>>>(gate_raw);
    dim3 gGrid(D_SAE / 128, NROWS / 128);  // (96, 16)
    gemm_enc<<<gGrid, 256>>>(x, W_enc, b_enc);
    topk128<<<NROWS, 256>>>();
    scan_kernel<<<BATCH, 256>>>();
    decode_kernel<<<NROWS, 192>>>(x, W_dec, b_dec, out_xhat);
    scatter_zlast<<<(BATCH * KTOP + 255) / 256, 256>>>(out_zlast);
    loss_kernel<<<1, 1024>>>(out_loss);
}

// round 8
// speedup vs baseline: 1.3632x; 1.0433x over previous
#include <cuda_runtime.h>
#include <cstdint>

#define D_IN   768
#define D_SAE  12288
#define T_LEN  64
#define KTOP   64
#define BATCH  32
#define NROWS  (BATCH * T_LEN)   // 2048

// ---------------- scratch (static device globals; no allocations) ----------------
__device__ __align__(16) float g_pre[(size_t)NROWS * D_SAE];     // 96 MB (exact fp32)
__device__ float g_gate[D_SAE];
__device__ int   g_topidx[NROWS * 128];   // SORTED by composite desc
__device__ float g_topval[NROWS * 128];
__device__ int   g_zidx[NROWS * KTOP];
__device__ float g_zval[NROWS * KTOP];
__device__ float g_rowloss[NROWS];

// ---------------- helpers ----------------
__device__ __forceinline__ unsigned long long pack2(float x, float y) {
    unsigned long long r;
    asm("mov.b64 %0, {%1, %2};" : "=l"(r) : "f"(x), "f"(y));
    return r;
}
__device__ __forceinline__ float2 unpack2(unsigned long long v) {
    float2 f;
    asm("mov.b64 {%0, %1}, %2;" : "=f"(f.x), "=f"(f.y) : "l"(v));
    return f;
}
__device__ __forceinline__ void fma2(unsigned long long& c, unsigned long long a, unsigned long long b) {
    asm("fma.rn.f32x2 %0, %1, %2, %0;" : "+l"(c) : "l"(a), "l"(b));
}
__device__ __forceinline__ unsigned int fkey(float v) {
    unsigned int u = __float_as_uint(v);
    return (u & 0x80000000u) ? ~u : (u | 0x80000000u);
}
__device__ __forceinline__ float keyToFloat(unsigned int k) {
    unsigned int u = (k & 0x80000000u) ? (k & 0x7FFFFFFFu) : ~k;
    return __uint_as_float(u);
}
// larger == (greater value) or (equal value, smaller index)  [jax top_k tie rule]
__device__ __forceinline__ unsigned long long makeComp(float v, int idx) {
    return ((unsigned long long)fkey(v) << 32) | (unsigned long long)(0xFFFFFFFFu - (unsigned int)idx);
}

// ======================================================================
// Kernel A: fp32 GEMM (proven variant; at the FFMA2 rt=3 roofline).
// ======================================================================
__global__ __launch_bounds__(256, 1) void gemm_enc(const float* __restrict__ X,
                                                   const float* __restrict__ W,
                                                   const float* __restrict__ bias) {
    __shared__ __align__(16) float As[2][16][128];
    __shared__ __align__(16) float Bs[2][16][128];

    const int tid  = threadIdx.x;
    const int row0 = blockIdx.y * 128;
    const int col0 = blockIdx.x * 128;
    const int tx = tid & 15, ty = tid >> 4;

    const int aRow = tid >> 2;
    const int aCol = (tid & 3) * 4;
    const int bRow = tid >> 5;
    const int bCol = (tid & 31) * 4;

    const float* Aptr = X + (size_t)row0 * D_IN;
    const float* Bptr = W + col0;

    float4 a0, a1, b0, b1;
    a0 = *(const float4*)(Aptr + (size_t)aRow * D_IN + aCol);
    a1 = *(const float4*)(Aptr + (size_t)(aRow + 64) * D_IN + aCol);
    b0 = *(const float4*)(Bptr + (size_t)bRow * D_SAE + bCol);
    b1 = *(const float4*)(Bptr + (size_t)(bRow + 8) * D_SAE + bCol);
    As[0][aCol + 0][aRow] = a0.x; As[0][aCol + 1][aRow] = a0.y;
    As[0][aCol + 2][aRow] = a0.z; As[0][aCol + 3][aRow] = a0.w;
    As[0][aCol + 0][aRow + 64] = a1.x; As[0][aCol + 1][aRow + 64] = a1.y;
    As[0][aCol + 2][aRow + 64] = a1.z; As[0][aCol + 3][aRow + 64] = a1.w;
    *(float4*)&Bs[0][bRow][bCol]     = b0;
    *(float4*)&Bs[0][bRow + 8][bCol] = b1;
    __syncthreads();

    unsigned long long cc[4][8];
#pragma unroll
    for (int i = 0; i < 4; ++i)
#pragma unroll
        for (int j = 0; j < 8; ++j) cc[i][j] = 0ull;

    const int NKT = D_IN / 16;  // 48
    for (int kt = 0; kt < NKT; ++kt) {
        const int cur = kt & 1;
        if (kt < NKT - 1) {
            const int k0 = (kt + 1) * 16;
            a0 = *(const float4*)(Aptr + (size_t)aRow * D_IN + k0 + aCol);
            a1 = *(const float4*)(Aptr + (size_t)(aRow + 64) * D_IN + k0 + aCol);
            b0 = *(const float4*)(Bptr + (size_t)(k0 + bRow) * D_SAE + bCol);
            b1 = *(const float4*)(Bptr + (size_t)(k0 + bRow + 8) * D_SAE + bCol);
        }
#pragma unroll
        for (int k = 0; k < 16; ++k) {
            ulonglong2 aa01 = *(const ulonglong2*)&As[cur][k][ty * 4];
            ulonglong2 aa23 = *(const ulonglong2*)&As[cur][k][64 + ty * 4];
            float4 bv0 = *(const float4*)&Bs[cur][k][tx * 4];
            float4 bv1 = *(const float4*)&Bs[cur][k][64 + tx * 4];
            unsigned long long av[4] = {aa01.x, aa01.y, aa23.x, aa23.y};
            unsigned long long bb[8] = {pack2(bv0.x, bv0.x), pack2(bv0.y, bv0.y),
                                        pack2(bv0.z, bv0.z), pack2(bv0.w, bv0.w),
                                        pack2(bv1.x, bv1.x), pack2(bv1.y, bv1.y),
                                        pack2(bv1.z, bv1.z), pack2(bv1.w, bv1.w)};
#pragma unroll
            for (int i = 0; i < 4; ++i)
#pragma unroll
                for (int j = 0; j < 8; ++j) fma2(cc[i][j], av[i], bb[j]);
        }
        if (kt < NKT - 1) {
            const int nxt = cur ^ 1;
            As[nxt][aCol + 0][aRow] = a0.x; As[nxt][aCol + 1][aRow] = a0.y;
            As[nxt][aCol + 2][aRow] = a0.z; As[nxt][aCol + 3][aRow] = a0.w;
            As[nxt][aCol + 0][aRow + 64] = a1.x; As[nxt][aCol + 1][aRow + 64] = a1.y;
            As[nxt][aCol + 2][aRow + 64] = a1.z; As[nxt][aCol + 3][aRow + 64] = a1.w;
            *(float4*)&Bs[nxt][bRow][bCol]     = b0;
            *(float4*)&Bs[nxt][bRow + 8][bCol] = b1;
        }
        __syncthreads();
    }

    float bc[8];
#pragma unroll
    for (int j = 0; j < 8; ++j) bc[j] = bias[col0 + (j >> 2) * 64 + tx * 4 + (j & 3)];

#pragma unroll
    for (int i = 0; i < 4; ++i) {
        const int m = (i >> 1) * 64 + ty * 4 + (i & 1) * 2;
        float2 v[8];
#pragma unroll
        for (int j = 0; j < 8; ++j) v[j] = unpack2(cc[i][j]);
        size_t base = (size_t)(row0 + m) * D_SAE + col0;
        float4 o;
        o.x = v[0].x + bc[0]; o.y = v[1].x + bc[1]; o.z = v[2].x + bc[2]; o.w = v[3].x + bc[3];
        *(float4*)&g_pre[base + tx * 4] = o;
        o.x = v[4].x + bc[4]; o.y = v[5].x + bc[5]; o.z = v[6].x + bc[6]; o.w = v[7].x + bc[7];
        *(float4*)&g_pre[base + 64 + tx * 4] = o;
        base += D_SAE;
        o.x = v[0].y + bc[0]; o.y = v[1].y + bc[1]; o.z = v[2].y + bc[2]; o.w = v[3].y + bc[3];
        *(float4*)&g_pre[base + tx * 4] = o;
        o.x = v[4].y + bc[4]; o.y = v[5].y + bc[5]; o.z = v[6].y + bc[6]; o.w = v[7].y + bc[7];
        *(float4*)&g_pre[base + 64 + tx * 4] = o;
    }
}

// ======================================================================
// Kernel B: exact top-128 per row, emitted SORTED by composite desc.
// Single DRAM pass (row held in regs), then 128x128 rank sort in smem.
// ======================================================================
#define TK_CAP 2816
__global__ __launch_bounds__(256) void topk128() {
    __shared__ unsigned int hist[4096];
    __shared__ __align__(16) unsigned long long cand[TK_CAP];
    __shared__ unsigned int chunkSum[16];
    __shared__ int s_bin;
    __shared__ unsigned int s_cntHi, s_cntCand;
    __shared__ int sIdx[128];
    __shared__ float sVal[128];
    __shared__ __align__(16) unsigned long long sComp[128];

    const int row = blockIdx.x, tid = threadIdx.x;
    const float* rp = g_pre + (size_t)row * D_SAE;

    for (int i = tid; i < 4096; i += 256) hist[i] = 0;
    if (tid == 0) { s_cntHi = 0; s_cntCand = 0; }
    __syncthreads();

    float v[48];
#pragma unroll
    for (int i = 0; i < 12; ++i) {
        const float4 q = *(const float4*)(rp + (size_t)(tid + i * 256) * 4);
        v[i * 4 + 0] = q.x; v[i * 4 + 1] = q.y; v[i * 4 + 2] = q.z; v[i * 4 + 3] = q.w;
    }
#pragma unroll
    for (int i = 0; i < 48; ++i) atomicAdd(&hist[fkey(v[i]) >> 20], 1u);
    __syncthreads();

    if (tid < 16) {
        unsigned int s = 0;
        for (int j = 0; j < 256; ++j) s += hist[tid * 256 + j];
        chunkSum[tid] = s;
    }
    __syncthreads();
    if (tid == 0) {
        unsigned int cum = 0; int cb;
        for (cb = 15; cb > 0; --cb) {
            if (cum + chunkSum[cb] >= 128u) break;
            cum += chunkSum[cb];
        }
        int bin;
        for (bin = cb * 256 + 255; bin > cb * 256; --bin) {
            if (cum + hist[bin] >= 128u) break;
            cum += hist[bin];
        }
        s_bin = bin;
    }
    __syncthreads();

    const int tb = s_bin;
#pragma unroll
    for (int i = 0; i < 48; ++i) {
        const unsigned int k = fkey(v[i]);
        const int bin = (int)(k >> 20);
        if (bin >= tb) {
            const int idx = (tid + (i >> 2) * 256) * 4 + (i & 3);
            if (bin > tb) {
                unsigned int p = atomicAdd(&s_cntHi, 1u);
                sIdx[p] = idx; sVal[p] = v[i];
            } else {
                unsigned int q = atomicAdd(&s_cntCand, 1u);
                if (q < TK_CAP) cand[q] = makeComp(v[i], idx);
            }
        }
    }
    __syncthreads();

    const int need = 128 - (int)s_cntHi;
    const int nc = min((int)s_cntCand, TK_CAP);
    for (int c = tid; c < nc; c += 256) {
        const unsigned long long me = cand[c];
        int r = 0;
        for (int j = 0; j < nc; ++j) r += (cand[j] > me);
        if (r < need) {
            const int pos = (int)s_cntHi + r;
            sIdx[pos] = (int)(0xFFFFFFFFu - (unsigned int)me);
            sVal[pos] = keyToFloat((unsigned int)(me >> 32));
        }
    }
    __syncthreads();

    // ---- sort the 128 entries by composite (exact rank placement) ----
    if (tid < 128) sComp[tid] = makeComp(sVal[tid], sIdx[tid]);
    __syncthreads();
    if (tid < 128) {
        const unsigned long long me = sComp[tid];
        int r = 0;
#pragma unroll
        for (int j = 0; j < 128; j += 8) {
            const ulonglong2 c0 = *(const ulonglong2*)&sComp[j];
            const ulonglong2 c1 = *(const ulonglong2*)&sComp[j + 2];
            const ulonglong2 c2 = *(const ulonglong2*)&sComp[j + 4];
            const ulonglong2 c3 = *(const ulonglong2*)&sComp[j + 6];
            r += (c0.x > me) + (c0.y > me) + (c1.x > me) + (c1.y > me)
               + (c2.x > me) + (c2.y > me) + (c3.x > me) + (c3.y > me);
        }
        g_topidx[row * 128 + r] = sIdx[tid];
        g_topval[row * 128 + r] = sVal[tid];
    }
}

// ======================================================================
// gate precompute + output-zero kernels
// ======================================================================
__global__ __launch_bounds__(256) void gate_kernel(const float* __restrict__ gate_raw) {
    const int i = blockIdx.x * 256 + threadIdx.x;
    if (i < D_SAE) g_gate[i] = 1.0f / (1.0f + expf(-gate_raw[i]));
}
__global__ void zero_half(float* __restrict__ z) {
    const int i = blockIdx.x * blockDim.x + threadIdx.x;
    if (i < BATCH * D_SAE / 2) z[i] = 0.0f;
}

// ======================================================================
// Kernel C: sequential scan with n=128 candidates:
// 64 prev (gated) + first 64 non-dup entries of the SORTED top-128.
// (top64(y) ⊆ P ∪ top64 of pre among non-P; sorted list gives the latter.)
// ======================================================================
__global__ __launch_bounds__(256) void scan_kernel() {
    __shared__ unsigned int bitmap[D_SAE / 32];
    __shared__ int prevIdx[KTOP];
    __shared__ float prevVal[KTOP];
    __shared__ __align__(16) unsigned long long cand[128];
    __shared__ int tmpIdx[KTOP];
    __shared__ float tmpVal[KTOP];
    __shared__ int warpCnt[4];

    const int b = blockIdx.x, tid = threadIdx.x, lane = tid & 31, w = tid >> 5;
    for (int i = tid; i < D_SAE / 32; i += 256) bitmap[i] = 0;
    int nprev = 0;
    __syncthreads();

    for (int t = 0; t < T_LEN; ++t) {
        const int row = b * T_LEN + t;
        if (tid < 128) cand[tid] = 0ull;   // sentinels
        __syncthreads();

        // prev candidates (slots 0..63)
        if (tid < nprev) {
            const int idx = prevIdx[tid];
            const float pre = g_pre[(size_t)row * D_SAE + idx];
            cand[tid] = makeComp(g_gate[idx] * prevVal[tid] + pre, idx);
        }
        // new candidates: first 64 non-dup of sorted top-128 (slots 64..127)
        int nIdx = 0; float nVal = 0.f; int flag = 0;
        if (tid < 128) {
            nIdx = g_topidx[row * 128 + tid];
            nVal = g_topval[row * 128 + tid];
            flag = !((bitmap[nIdx >> 5] >> (nIdx & 31)) & 1u);
        }
        const unsigned bal = __ballot_sync(0xFFFFFFFFu, flag);
        if (tid < 128 && lane == 0) warpCnt[w] = __popc(bal);
        __syncthreads();
        if (tid < 128 && flag) {
            int off = __popc(bal & ((1u << lane) - 1));
            for (int q = 0; q < w; ++q) off += warpCnt[q];
            if (off < KTOP) cand[64 + off] = makeComp(nVal, nIdx);
        }
        __syncthreads();

        // exact rank over 128 candidates
        if (tid < 128) {
            const unsigned long long me = cand[tid];
            int r = 0;
#pragma unroll
            for (int j = 0; j < 128; j += 8) {
                const ulonglong2 c0 = *(const ulonglong2*)&cand[j];
                const ulonglong2 c1 = *(const ulonglong2*)&cand[j + 2];
                const ulonglong2 c2 = *(const ulonglong2*)&cand[j + 4];
                const ulonglong2 c3 = *(const ulonglong2*)&cand[j + 6];
                r += (c0.x > me) + (c0.y > me) + (c1.x > me) + (c1.y > me)
                   + (c2.x > me) + (c2.y > me) + (c3.x > me) + (c3.y > me);
            }
            if (me != 0ull && r < KTOP) {
                tmpIdx[r] = (int)(0xFFFFFFFFu - (unsigned int)me);
                tmpVal[r] = fmaxf(keyToFloat((unsigned int)(me >> 32)), 0.0f);
            }
        }
        __syncthreads();

        if (tid < nprev) atomicAnd(&bitmap[prevIdx[tid] >> 5], ~(1u << (prevIdx[tid] & 31)));
        __syncthreads();

        if (tid < KTOP) {
            const int idx = tmpIdx[tid];
            const float vv = tmpVal[tid];
            prevIdx[tid] = idx; prevVal[tid] = vv;
            atomicOr(&bitmap[idx >> 5], 1u << (idx & 31));
            g_zidx[row * KTOP + tid] = idx;
            g_zval[row * KTOP + tid] = vv;
        }
        nprev = KTOP;
        __syncthreads();
    }
}

// ======================================================================
// Kernel D: sparse decode + per-row squared error. (xhat only 4B-aligned)
// ======================================================================
__global__ __launch_bounds__(192) void decode_kernel(const float* __restrict__ X,
                                                     const float* __restrict__ Wd,
                                                     const float* __restrict__ b_dec,
                                                     float* __restrict__ xhat) {
    __shared__ int sIdx[KTOP];
    __shared__ float sVal[KTOP];
    __shared__ float red[192];
    const int row = blockIdx.x, tid = threadIdx.x;
    if (tid < KTOP) {
        sIdx[tid] = g_zidx[row * KTOP + tid];
        sVal[tid] = g_zval[row * KTOP + tid];
    }
    __syncthreads();

    float4 acc = *(const float4*)(b_dec + tid * 4);
#pragma unroll 4
    for (int k = 0; k < KTOP; ++k) {
        const float v = sVal[k];
        const float4 wv = *(const float4*)(Wd + (size_t)sIdx[k] * D_IN + tid * 4);
        acc.x += v * wv.x; acc.y += v * wv.y; acc.z += v * wv.z; acc.w += v * wv.w;
    }
    float* op = xhat + (size_t)row * D_IN + tid * 4;
    op[0] = acc.x; op[1] = acc.y; op[2] = acc.z; op[3] = acc.w;

    const float4 xv = *(const float4*)(X + (size_t)row * D_IN + tid * 4);
    const float dx = acc.x - xv.x, dy = acc.y - xv.y, dz = acc.z - xv.z, dw = acc.w - xv.w;
    red[tid] = dx * dx + dy * dy + dz * dz + dw * dw;
    __syncthreads();
    for (int s = 96; s >= 6; s >>= 1) {
        if (tid < s) red[tid] += red[tid + s];
        __syncthreads();
    }
    if (tid == 0) {
        float total = 0.f;
        for (int i = 0; i < 6; ++i) total += red[i];
        g_rowloss[row] = total;
    }
}

// ======================================================================
// Finalization
// ======================================================================
__global__ void scatter_zlast(float* __restrict__ z) {
    const int gid = blockIdx.x * blockDim.x + threadIdx.x;
    if (gid < BATCH * KTOP) {
        const int b = gid >> 6, k = gid & 63;
        const int row = b * T_LEN + (T_LEN - 1);
        z[(size_t)b * D_SAE + g_zidx[row * KTOP + k]] = g_zval[row * KTOP + k];
    }
}
__global__ __launch_bounds__(1024) void loss_kernel(float* __restrict__ out) {
    __shared__ float red[1024];
    const int tid = threadIdx.x;
    red[tid] = g_rowloss[tid] + g_rowloss[tid + 1024];
    __syncthreads();
    for (int s = 512; s > 0; s >>= 1) {
        if (tid < s) red[tid] += red[tid + s];
        __syncthreads();
    }
    if (tid == 0) out[0] = red[0] / (float)NROWS;
}

// ======================================================================
extern "C" void kernel_launch(void* const* d_in, const int* in_sizes, int n_in,
                              void* d_out, int out_size) {
    const float* x        = (const float*)d_in[0];
    const float* W_enc    = (const float*)d_in[1];
    const float* W_dec    = (const float*)d_in[2];
    const float* b_enc    = (const float*)d_in[3];
    const float* b_dec    = (const float*)d_in[4];
    const float* gate_raw = (const float*)d_in[5];

    float* out       = (float*)d_out;
    float* out_loss  = out;
    float* out_xhat  = out + 1;
    float* out_zlast = out + 1 + (size_t)NROWS * D_IN;

    const int halfN = BATCH * D_SAE / 2;
    // launch order: scan is launch #4 so ncu profiles it this round
    gate_kernel<<<(D_SAE + 255) / 256, 256>>>(gate_raw);
    dim3 gGrid(D_SAE / 128, NROWS / 128);  // (96, 16)
    gemm_enc<<<gGrid, 256>>>(x, W_enc, b_enc);
    topk128<<<NROWS, 256>>>();
    scan_kernel<<<BATCH, 256>>>();
    decode_kernel<<<NROWS, 192>>>(x, W_dec, b_dec, out_xhat);
    zero_half<<<(halfN + 255) / 256, 256>>>(out_zlast);
    zero_half<<<(halfN + 255) / 256, 256>>>(out_zlast + halfN);
    scatter_zlast<<<(BATCH * KTOP + 255) / 256, 256>>>(out_zlast);
    loss_kernel<<<1, 1024>>>(out_loss);
}

// round 9
// speedup vs baseline: 1.4180x; 1.0402x over previous
#include <cuda_runtime.h>
#include <cstdint>

#define D_IN   768
#define D_SAE  12288
#define T_LEN  64
#define KTOP   64
#define BATCH  32
#define NROWS  (BATCH * T_LEN)   // 2048

// ---------------- scratch (static device globals; no allocations) ----------------
__device__ __align__(16) float g_pre[(size_t)NROWS * D_SAE];     // 96 MB (exact fp32)
__device__ int   g_topidx[NROWS * 128];   // SORTED by composite desc
__device__ float g_topval[NROWS * 128];
__device__ int   g_zidx[NROWS * KTOP];
__device__ float g_zval[NROWS * KTOP];
__device__ float g_rowloss[NROWS];

// ---------------- helpers ----------------
__device__ __forceinline__ unsigned long long pack2(float x, float y) {
    unsigned long long r;
    asm("mov.b64 %0, {%1, %2};" : "=l"(r) : "f"(x), "f"(y));
    return r;
}
__device__ __forceinline__ float2 unpack2(unsigned long long v) {
    float2 f;
    asm("mov.b64 {%0, %1}, %2;" : "=f"(f.x), "=f"(f.y) : "l"(v));
    return f;
}
__device__ __forceinline__ void fma2(unsigned long long& c, unsigned long long a, unsigned long long b) {
    asm("fma.rn.f32x2 %0, %1, %2, %0;" : "+l"(c) : "l"(a), "l"(b));
}
__device__ __forceinline__ unsigned int fkey(float v) {
    unsigned int u = __float_as_uint(v);
    return (u & 0x80000000u) ? ~u : (u | 0x80000000u);
}
__device__ __forceinline__ float keyToFloat(unsigned int k) {
    unsigned int u = (k & 0x80000000u) ? (k & 0x7FFFFFFFu) : ~k;
    return __uint_as_float(u);
}
// larger == (greater value) or (equal value, smaller index)  [jax top_k tie rule]
__device__ __forceinline__ unsigned long long makeComp(float v, int idx) {
    return ((unsigned long long)fkey(v) << 32) | (unsigned long long)(0xFFFFFFFFu - (unsigned int)idx);
}

// ======================================================================
// Kernel A: fp32 GEMM (proven variant; at the FFMA2 rt=3 roofline).
// ======================================================================
__global__ __launch_bounds__(256, 1) void gemm_enc(const float* __restrict__ X,
                                                   const float* __restrict__ W,
                                                   const float* __restrict__ bias) {
    __shared__ __align__(16) float As[2][16][128];
    __shared__ __align__(16) float Bs[2][16][128];

    const int tid  = threadIdx.x;
    const int row0 = blockIdx.y * 128;
    const int col0 = blockIdx.x * 128;
    const int tx = tid & 15, ty = tid >> 4;

    const int aRow = tid >> 2;
    const int aCol = (tid & 3) * 4;
    const int bRow = tid >> 5;
    const int bCol = (tid & 31) * 4;

    const float* Aptr = X + (size_t)row0 * D_IN;
    const float* Bptr = W + col0;

    float4 a0, a1, b0, b1;
    a0 = *(const float4*)(Aptr + (size_t)aRow * D_IN + aCol);
    a1 = *(const float4*)(Aptr + (size_t)(aRow + 64) * D_IN + aCol);
    b0 = *(const float4*)(Bptr + (size_t)bRow * D_SAE + bCol);
    b1 = *(const float4*)(Bptr + (size_t)(bRow + 8) * D_SAE + bCol);
    As[0][aCol + 0][aRow] = a0.x; As[0][aCol + 1][aRow] = a0.y;
    As[0][aCol + 2][aRow] = a0.z; As[0][aCol + 3][aRow] = a0.w;
    As[0][aCol + 0][aRow + 64] = a1.x; As[0][aCol + 1][aRow + 64] = a1.y;
    As[0][aCol + 2][aRow + 64] = a1.z; As[0][aCol + 3][aRow + 64] = a1.w;
    *(float4*)&Bs[0][bRow][bCol]     = b0;
    *(float4*)&Bs[0][bRow + 8][bCol] = b1;
    __syncthreads();

    unsigned long long cc[4][8];
#pragma unroll
    for (int i = 0; i < 4; ++i)
#pragma unroll
        for (int j = 0; j < 8; ++j) cc[i][j] = 0ull;

    const int NKT = D_IN / 16;  // 48
    for (int kt = 0; kt < NKT; ++kt) {
        const int cur = kt & 1;
        if (kt < NKT - 1) {
            const int k0 = (kt + 1) * 16;
            a0 = *(const float4*)(Aptr + (size_t)aRow * D_IN + k0 + aCol);
            a1 = *(const float4*)(Aptr + (size_t)(aRow + 64) * D_IN + k0 + aCol);
            b0 = *(const float4*)(Bptr + (size_t)(k0 + bRow) * D_SAE + bCol);
            b1 = *(const float4*)(Bptr + (size_t)(k0 + bRow + 8) * D_SAE + bCol);
        }
#pragma unroll
        for (int k = 0; k < 16; ++k) {
            ulonglong2 aa01 = *(const ulonglong2*)&As[cur][k][ty * 4];
            ulonglong2 aa23 = *(const ulonglong2*)&As[cur][k][64 + ty * 4];
            float4 bv0 = *(const float4*)&Bs[cur][k][tx * 4];
            float4 bv1 = *(const float4*)&Bs[cur][k][64 + tx * 4];
            unsigned long long av[4] = {aa01.x, aa01.y, aa23.x, aa23.y};
            unsigned long long bb[8] = {pack2(bv0.x, bv0.x), pack2(bv0.y, bv0.y),
                                        pack2(bv0.z, bv0.z), pack2(bv0.w, bv0.w),
                                        pack2(bv1.x, bv1.x), pack2(bv1.y, bv1.y),
                                        pack2(bv1.z, bv1.z), pack2(bv1.w, bv1.w)};
#pragma unroll
            for (int i = 0; i < 4; ++i)
#pragma unroll
                for (int j = 0; j < 8; ++j) fma2(cc[i][j], av[i], bb[j]);
        }
        if (kt < NKT - 1) {
            const int nxt = cur ^ 1;
            As[nxt][aCol + 0][aRow] = a0.x; As[nxt][aCol + 1][aRow] = a0.y;
            As[nxt][aCol + 2][aRow] = a0.z; As[nxt][aCol + 3][aRow] = a0.w;
            As[nxt][aCol + 0][aRow + 64] = a1.x; As[nxt][aCol + 1][aRow + 64] = a1.y;
            As[nxt][aCol + 2][aRow + 64] = a1.z; As[nxt][aCol + 3][aRow + 64] = a1.w;
            *(float4*)&Bs[nxt][bRow][bCol]     = b0;
            *(float4*)&Bs[nxt][bRow + 8][bCol] = b1;
        }
        __syncthreads();
    }

    float bc[8];
#pragma unroll
    for (int j = 0; j < 8; ++j) bc[j] = bias[col0 + (j >> 2) * 64 + tx * 4 + (j & 3)];

#pragma unroll
    for (int i = 0; i < 4; ++i) {
        const int m = (i >> 1) * 64 + ty * 4 + (i & 1) * 2;
        float2 v[8];
#pragma unroll
        for (int j = 0; j < 8; ++j) v[j] = unpack2(cc[i][j]);
        size_t base = (size_t)(row0 + m) * D_SAE + col0;
        float4 o;
        o.x = v[0].x + bc[0]; o.y = v[1].x + bc[1]; o.z = v[2].x + bc[2]; o.w = v[3].x + bc[3];
        *(float4*)&g_pre[base + tx * 4] = o;
        o.x = v[4].x + bc[4]; o.y = v[5].x + bc[5]; o.z = v[6].x + bc[6]; o.w = v[7].x + bc[7];
        *(float4*)&g_pre[base + 64 + tx * 4] = o;
        base += D_SAE;
        o.x = v[0].y + bc[0]; o.y = v[1].y + bc[1]; o.z = v[2].y + bc[2]; o.w = v[3].y + bc[3];
        *(float4*)&g_pre[base + tx * 4] = o;
        o.x = v[4].y + bc[4]; o.y = v[5].y + bc[5]; o.z = v[6].y + bc[6]; o.w = v[7].y + bc[7];
        *(float4*)&g_pre[base + 64 + tx * 4] = o;
    }
}

// ======================================================================
// Kernel B: exact top-128 per row, emitted SORTED by composite desc.
// Single DRAM pass (row held in regs; launch_bounds(256,2) => no spill).
// ======================================================================
#define TK_CAP 2816
__global__ __launch_bounds__(256, 2) void topk128() {
    __shared__ unsigned int hist[4096];
    __shared__ __align__(16) unsigned long long cand[TK_CAP];
    __shared__ unsigned int chunkSum[16];
    __shared__ int s_bin;
    __shared__ unsigned int s_cntHi, s_cntCand;
    __shared__ int sIdx[128];
    __shared__ float sVal[128];
    __shared__ __align__(16) unsigned long long sComp[128];

    const int row = blockIdx.x, tid = threadIdx.x;
    const float* rp = g_pre + (size_t)row * D_SAE;

    for (int i = tid; i < 4096; i += 256) hist[i] = 0;
    if (tid == 0) { s_cntHi = 0; s_cntCand = 0; }
    __syncthreads();

    float v[48];
#pragma unroll
    for (int i = 0; i < 12; ++i) {
        const float4 q = *(const float4*)(rp + (size_t)(tid + i * 256) * 4);
        v[i * 4 + 0] = q.x; v[i * 4 + 1] = q.y; v[i * 4 + 2] = q.z; v[i * 4 + 3] = q.w;
    }
#pragma unroll
    for (int i = 0; i < 48; ++i) atomicAdd(&hist[fkey(v[i]) >> 20], 1u);
    __syncthreads();

    if (tid < 16) {
        unsigned int s = 0;
        for (int j = 0; j < 256; ++j) s += hist[tid * 256 + j];
        chunkSum[tid] = s;
    }
    __syncthreads();
    if (tid == 0) {
        unsigned int cum = 0; int cb;
        for (cb = 15; cb > 0; --cb) {
            if (cum + chunkSum[cb] >= 128u) break;
            cum += chunkSum[cb];
        }
        int bin;
        for (bin = cb * 256 + 255; bin > cb * 256; --bin) {
            if (cum + hist[bin] >= 128u) break;
            cum += hist[bin];
        }
        s_bin = bin;
    }
    __syncthreads();

    const int tb = s_bin;
#pragma unroll
    for (int i = 0; i < 48; ++i) {
        const unsigned int k = fkey(v[i]);
        const int bin = (int)(k >> 20);
        if (bin >= tb) {
            const int idx = (tid + (i >> 2) * 256) * 4 + (i & 3);
            if (bin > tb) {
                unsigned int p = atomicAdd(&s_cntHi, 1u);
                sIdx[p] = idx; sVal[p] = v[i];
            } else {
                unsigned int q = atomicAdd(&s_cntCand, 1u);
                if (q < TK_CAP) cand[q] = makeComp(v[i], idx);
            }
        }
    }
    __syncthreads();

    const int need = 128 - (int)s_cntHi;
    const int nc = min((int)s_cntCand, TK_CAP);
    for (int c = tid; c < nc; c += 256) {
        const unsigned long long me = cand[c];
        int r = 0;
        for (int j = 0; j < nc; ++j) r += (cand[j] > me);
        if (r < need) {
            const int pos = (int)s_cntHi + r;
            sIdx[pos] = (int)(0xFFFFFFFFu - (unsigned int)me);
            sVal[pos] = keyToFloat((unsigned int)(me >> 32));
        }
    }
    __syncthreads();

    if (tid < 128) sComp[tid] = makeComp(sVal[tid], sIdx[tid]);
    __syncthreads();
    if (tid < 128) {
        const unsigned long long me = sComp[tid];
        int r = 0;
#pragma unroll
        for (int j = 0; j < 128; j += 8) {
            const ulonglong2 c0 = *(const ulonglong2*)&sComp[j];
            const ulonglong2 c1 = *(const ulonglong2*)&sComp[j + 2];
            const ulonglong2 c2 = *(const ulonglong2*)&sComp[j + 4];
            const ulonglong2 c3 = *(const ulonglong2*)&sComp[j + 6];
            r += (c0.x > me) + (c0.y > me) + (c1.x > me) + (c1.y > me)
               + (c2.x > me) + (c2.y > me) + (c3.x > me) + (c3.y > me);
        }
        g_topidx[row * 128 + r] = sIdx[tid];
        g_topval[row * 128 + r] = sVal[tid];
    }
}

// ======================================================================
// Kernel C: sequential scan, 128 threads, 4 syncs/step, prefetched
// top-lists, inline sigmoid, fused z_last zero+scatter.
// ======================================================================
__global__ __launch_bounds__(128) void scan_kernel(const float* __restrict__ gate_raw,
                                                   float* __restrict__ z_last) {
    __shared__ unsigned int bitmap[D_SAE / 32];
    __shared__ int prevIdx[KTOP];
    __shared__ float prevVal[KTOP];
    __shared__ __align__(16) unsigned long long cand[128];
    __shared__ int tmpIdx[KTOP];
    __shared__ float tmpVal[KTOP];
    __shared__ int warpCnt[4];

    const int b = blockIdx.x, tid = threadIdx.x, lane = tid & 31, w = tid >> 5;

    // zero this batch's z_last slice (same CTA later scatters into it)
    for (int i = tid; i < D_SAE; i += 128) z_last[(size_t)b * D_SAE + i] = 0.0f;
    for (int i = tid; i < D_SAE / 32; i += 128) bitmap[i] = 0;
    if (tid < 64) cand[tid] = 0ull;   // t=0 has no prev candidates
    int nprev = 0;

    // preload step-0 top list
    int nIdx = g_topidx[(size_t)(b * T_LEN) * 128 + tid];
    float nVal = g_topval[(size_t)(b * T_LEN) * 128 + tid];
    __syncthreads();

    for (int t = 0; t < T_LEN; ++t) {
        const int row = b * T_LEN + t;

        // prev candidates (slots 0..63), inline sigmoid gate
        if (tid < nprev) {
            const int idx = prevIdx[tid];
            const float pre = g_pre[(size_t)row * D_SAE + idx];
            const float gate = 1.0f / (1.0f + __expf(-gate_raw[idx]) *
                                       (1.0f));  // placeholder shape; replaced below
            // NOTE: use exact expf for bit-compat with earlier rounds
            const float gate_e = 1.0f / (1.0f + expf(-gate_raw[idx]));
            (void)gate;
            cand[tid] = makeComp(gate_e * prevVal[tid] + pre, idx);
        }
        // new candidates: dup flags against prev selection
        const int flag = !((bitmap[nIdx >> 5] >> (nIdx & 31)) & 1u);
        const unsigned bal = __ballot_sync(0xFFFFFFFFu, flag);
        if (lane == 0) warpCnt[w] = __popc(bal);
        __syncthreads();

        int off = __popc(bal & ((1u << lane) - 1));
#pragma unroll
        for (int q = 0; q < 4; ++q) off += (q < w) ? warpCnt[q] : 0;
        if (flag && off < KTOP) cand[64 + off] = makeComp(nVal, nIdx);
        __syncthreads();

        // clear old bitmap bits (safe: flags already consumed) + prefetch t+1 list
        if (tid < nprev) atomicAnd(&bitmap[prevIdx[tid] >> 5], ~(1u << (prevIdx[tid] & 31)));
        int nIdx2 = 0; float nVal2 = 0.0f;
        if (t + 1 < T_LEN) {
            nIdx2 = g_topidx[(size_t)(row + 1) * 128 + tid];
            nVal2 = g_topval[(size_t)(row + 1) * 128 + tid];
        }

        // exact rank over 128 candidates
        {
            const unsigned long long me = cand[tid];
            int r = 0;
#pragma unroll
            for (int j = 0; j < 128; j += 8) {
                const ulonglong2 c0 = *(const ulonglong2*)&cand[j];
                const ulonglong2 c1 = *(const ulonglong2*)&cand[j + 2];
                const ulonglong2 c2 = *(const ulonglong2*)&cand[j + 4];
                const ulonglong2 c3 = *(const ulonglong2*)&cand[j + 6];
                r += (c0.x > me) + (c0.y > me) + (c1.x > me) + (c1.y > me)
                   + (c2.x > me) + (c2.y > me) + (c3.x > me) + (c3.y > me);
            }
            if (me != 0ull && r < KTOP) {
                tmpIdx[r] = (int)(0xFFFFFFFFu - (unsigned int)me);
                tmpVal[r] = fmaxf(keyToFloat((unsigned int)(me >> 32)), 0.0f);
            }
        }
        __syncthreads();

        if (tid < KTOP) {
            const int idx = tmpIdx[tid];
            const float vv = tmpVal[tid];
            prevIdx[tid] = idx; prevVal[tid] = vv;
            atomicOr(&bitmap[idx >> 5], 1u << (idx & 31));
            g_zidx[row * KTOP + tid] = idx;
            g_zval[row * KTOP + tid] = vv;
            if (t == T_LEN - 1) z_last[(size_t)b * D_SAE + idx] = vv;
        }
        nprev = KTOP;
        nIdx = nIdx2; nVal = nVal2;
        __syncthreads();
    }
}

// ======================================================================
// Kernel D: sparse decode + per-row squared error. (xhat only 4B-aligned)
// ======================================================================
__global__ __launch_bounds__(192) void decode_kernel(const float* __restrict__ X,
                                                     const float* __restrict__ Wd,
                                                     const float* __restrict__ b_dec,
                                                     float* __restrict__ xhat) {
    __shared__ int sIdx[KTOP];
    __shared__ float sVal[KTOP];
    __shared__ float red[192];
    const int row = blockIdx.x, tid = threadIdx.x;
    if (tid < KTOP) {
        sIdx[tid] = g_zidx[row * KTOP + tid];
        sVal[tid] = g_zval[row * KTOP + tid];
    }
    __syncthreads();

    float4 acc = *(const float4*)(b_dec + tid * 4);
#pragma unroll 4
    for (int k = 0; k < KTOP; ++k) {
        const float v = sVal[k];
        const float4 wv = *(const float4*)(Wd + (size_t)sIdx[k] * D_IN + tid * 4);
        acc.x += v * wv.x; acc.y += v * wv.y; acc.z += v * wv.z; acc.w += v * wv.w;
    }
    float* op = xhat + (size_t)row * D_IN + tid * 4;
    op[0] = acc.x; op[1] = acc.y; op[2] = acc.z; op[3] = acc.w;

    const float4 xv = *(const float4*)(X + (size_t)row * D_IN + tid * 4);
    const float dx = acc.x - xv.x, dy = acc.y - xv.y, dz = acc.z - xv.z, dw = acc.w - xv.w;
    red[tid] = dx * dx + dy * dy + dz * dz + dw * dw;
    __syncthreads();
    for (int s = 96; s >= 6; s >>= 1) {
        if (tid < s) red[tid] += red[tid + s];
        __syncthreads();
    }
    if (tid == 0) {
        float total = 0.f;
        for (int i = 0; i < 6; ++i) total += red[i];
        g_rowloss[row] = total;
    }
}

// ======================================================================
// Finalization
// ======================================================================
__global__ __launch_bounds__(1024) void loss_kernel(float* __restrict__ out) {
    __shared__ float red[1024];
    const int tid = threadIdx.x;
    red[tid] = g_rowloss[tid] + g_rowloss[tid + 1024];
    __syncthreads();
    for (int s = 512; s > 0; s >>= 1) {
        if (tid < s) red[tid] += red[tid + s];
        __syncthreads();
    }
    if (tid == 0) out[0] = red[0] / (float)NROWS;
}

// ======================================================================
extern "C" void kernel_launch(void* const* d_in, const int* in_sizes, int n_in,
                              void* d_out, int out_size) {
    const float* x        = (const float*)d_in[0];
    const float* W_enc    = (const float*)d_in[1];
    const float* W_dec    = (const float*)d_in[2];
    const float* b_enc    = (const float*)d_in[3];
    const float* b_dec    = (const float*)d_in[4];
    const float* gate_raw = (const float*)d_in[5];

    float* out       = (float*)d_out;
    float* out_loss  = out;
    float* out_xhat  = out + 1;
    float* out_zlast = out + 1 + (size_t)NROWS * D_IN;

    dim3 gGrid(D_SAE / 128, NROWS / 128);  // (96, 16)
    gemm_enc<<<gGrid, 256>>>(x, W_enc, b_enc);
    topk128<<<NROWS, 256>>>();
    scan_kernel<<<BATCH, 128>>>(gate_raw, out_zlast);
    decode_kernel<<<NROWS, 192>>>(x, W_dec, b_dec, out_xhat);
    loss_kernel<<<1, 1024>>>(out_loss);
}